// round 10
// baseline (speedup 1.0000x reference)
#include <cuda_runtime.h>
#include <cuda_bf16.h>
#include <stdint.h>

// qGPS: out[b] = sum_m prod_l eps[samples[b,l], m, l],  B=4096 L=256 D=2 M=64
//
// SINGLE fused kernel. log-domain GEMM on HMMA:
//   d[m,l] = log2(eps1/eps0) split bf16 hi+lo;  base2[m] = sum_l log2 eps0
//   out[b] = sum_m exp2(base2[m] + acc_hi[b,m] + acc_lo[b,m])
// Each CTA recomputes the d-table in smem (32K log2f, overlapped with the
// A-tile DRAM fetch), then does the 32x64x256 GEMM tile + exp2 epilogue.
// 128 CTAs x 256 threads; full m per CTA -> plain stores, no atomics.

#define NB 4096
#define NL 256
#define NM 64

// smem: Bh (64 rows x 512B swz) [0,32K)  Bl [32K,64K)  A (32 rows) [64K,80K)
//       base2 [80K,+256)  part [+256,+768)
#define SM_BH  0
#define SM_BL  32768
#define SM_A   65536
#define SM_B2  81920
#define SM_PT  82176
#define SMEM   82688

__device__ __forceinline__ uint32_t swz(int row, int byte_in_row) {
    return (uint32_t)(row * 512 + (byte_in_row ^ ((row & 7) << 4)));
}

__device__ __forceinline__ void mma16816(float* d, uint32_t a0, uint32_t a1,
                                         uint32_t a2, uint32_t a3,
                                         uint32_t b0, uint32_t b1)
{
    asm volatile(
        "mma.sync.aligned.m16n8k16.row.col.f32.bf16.bf16.f32 "
        "{%0,%1,%2,%3}, {%4,%5,%6,%7}, {%8,%9}, {%0,%1,%2,%3};"
        : "+f"(d[0]), "+f"(d[1]), "+f"(d[2]), "+f"(d[3])
        : "r"(a0), "r"(a1), "r"(a2), "r"(a3), "r"(b0), "r"(b1));
}

__global__ __launch_bounds__(256, 1)
void qgps_fused_kernel(const int* __restrict__ samples,
                       const float* __restrict__ eps,
                       float* __restrict__ out)
{
    extern __shared__ char smem[];
    const int tid  = threadIdx.x;
    const int wid  = tid >> 5;          // 0..7
    const int lane = tid & 31;
    const int t    = blockIdx.x;        // 128 CTAs x 32 batches

    // ---- issue A-tile loads first (DRAM latency hidden behind prep MUFU) ----
    const int4* src = (const int4*)(samples + (size_t)t * 32 * NL);
    int4 sa[4], sb[4];
#pragma unroll
    for (int it = 0; it < 4; it++) {
        int c = tid + it * 256;
        sa[it] = src[2 * c];
        sb[it] = src[2 * c + 1];
    }

    // ---- prep: build d hi/lo tables + base2 in smem ----
    // thread -> m = tid>>2 (one row), j = tid&3; 32 iters x 2 l's each
    {
        const int m = tid >> 2;
        const int j = tid & 3;
        const float* e0p = eps + m * NL;
        const float* e1p = eps + NM * NL + m * NL;
        float bsum = 0.0f;
#pragma unroll
        for (int i = 0; i < 32; i++) {
            int p = j + i * 4;                 // l-pair index, l = 2p, 2p+1
            float2 f0 = *(const float2*)(e0p + 2 * p);
            float2 f1 = *(const float2*)(e1p + 2 * p);
            float l00 = log2f(f0.x), l01 = log2f(f0.y);
            float l10 = log2f(f1.x), l11 = log2f(f1.y);
            float d0 = l10 - l00, d1 = l11 - l01;
            __nv_bfloat16 h0 = __float2bfloat16(d0);
            __nv_bfloat16 h1 = __float2bfloat16(d1);
            float r0 = d0 - __bfloat162float(h0);
            float r1 = d1 - __bfloat162float(h1);
            __nv_bfloat16 g0 = __float2bfloat16(r0);
            __nv_bfloat16 g1 = __float2bfloat16(r1);
            uint32_t hw = (uint32_t)__bfloat16_as_ushort(h0)
                        | ((uint32_t)__bfloat16_as_ushort(h1) << 16);
            uint32_t lw = (uint32_t)__bfloat16_as_ushort(g0)
                        | ((uint32_t)__bfloat16_as_ushort(g1) << 16);
            uint32_t a = swz(m, 4 * p);
            *(uint32_t*)(smem + SM_BH + a) = hw;
            *(uint32_t*)(smem + SM_BL + a) = lw;
            bsum += l00 + l01;
        }
        bsum += __shfl_xor_sync(0xffffffffu, bsum, 1);
        bsum += __shfl_xor_sync(0xffffffffu, bsum, 2);
        if (j == 0) *(float*)(smem + SM_B2 + m * 4) = bsum;
    }

    // ---- A convert + swizzled store (32 rows x 256 cols bf16 {0,1}) ----
#pragma unroll
    for (int it = 0; it < 4; it++) {
        int c   = tid + it * 256;
        int row = c >> 5;
        int cb  = (c & 31) * 16;
        uint32_t w0 = (uint32_t)sa[it].x * 0x3F80u + (uint32_t)sa[it].y * 0x3F800000u;
        uint32_t w1 = (uint32_t)sa[it].z * 0x3F80u + (uint32_t)sa[it].w * 0x3F800000u;
        uint32_t w2 = (uint32_t)sb[it].x * 0x3F80u + (uint32_t)sb[it].y * 0x3F800000u;
        uint32_t w3 = (uint32_t)sb[it].z * 0x3F80u + (uint32_t)sb[it].w * 0x3F800000u;
        *(uint4*)(smem + SM_A + swz(row, cb)) = make_uint4(w0, w1, w2, w3);
    }
    __syncthreads();

    // ---- MMA: warp = (row tile rt = wid&1) x (16-col quarter nh = wid>>1) ----
    const int rt   = wid & 1;
    const int nh   = wid >> 1;          // 0..3
    const int qrow = lane >> 2;
    const int qk   = (lane & 3) * 4;
    const int ar0  = rt * 16 + qrow;    // < 32
    const int ar1  = ar0 + 8;

    float ah[2][4] = {{0,0,0,0},{0,0,0,0}};
    float al[2][4] = {{0,0,0,0},{0,0,0,0}};

#pragma unroll
    for (int kk = 0; kk < 16; kk++) {
        int kb = kk * 32 + qk;
        uint32_t a0 = *(const uint32_t*)(smem + SM_A + swz(ar0, kb));
        uint32_t a1 = *(const uint32_t*)(smem + SM_A + swz(ar1, kb));
        uint32_t a2 = *(const uint32_t*)(smem + SM_A + swz(ar0, kb + 16));
        uint32_t a3 = *(const uint32_t*)(smem + SM_A + swz(ar1, kb + 16));
#pragma unroll
        for (int jj = 0; jj < 2; jj++) {
            int br = (nh * 2 + jj) * 8 + qrow;   // < 64
            uint32_t bh0 = *(const uint32_t*)(smem + SM_BH + swz(br, kb));
            uint32_t bh1 = *(const uint32_t*)(smem + SM_BH + swz(br, kb + 16));
            mma16816(ah[jj], a0, a1, a2, a3, bh0, bh1);
            uint32_t bl0 = *(const uint32_t*)(smem + SM_BL + swz(br, kb));
            uint32_t bl1 = *(const uint32_t*)(smem + SM_BL + swz(br, kb + 16));
            mma16816(al[jj], a0, a1, a2, a3, bl0, bl1);
        }
    }

    // ---- epilogue: exp2(acc_h + acc_l + base2), reduce this warp's 16 cols ----
    const float* b2 = (const float*)(smem + SM_B2);
    float s0 = 0.0f, s1 = 0.0f;
#pragma unroll
    for (int jj = 0; jj < 2; jj++) {
        int c0 = (nh * 2 + jj) * 8 + (lane & 3) * 2;
        float ba = b2[c0], bb = b2[c0 + 1];
        float e0, e1, e2, e3;
        asm("ex2.approx.ftz.f32 %0, %1;" : "=f"(e0) : "f"(ah[jj][0] + al[jj][0] + ba));
        asm("ex2.approx.ftz.f32 %0, %1;" : "=f"(e1) : "f"(ah[jj][1] + al[jj][1] + bb));
        asm("ex2.approx.ftz.f32 %0, %1;" : "=f"(e2) : "f"(ah[jj][2] + al[jj][2] + ba));
        asm("ex2.approx.ftz.f32 %0, %1;" : "=f"(e3) : "f"(ah[jj][3] + al[jj][3] + bb));
        s0 += e0 + e1;      // row ar0
        s1 += e2 + e3;      // row ar1
    }
#pragma unroll
    for (int off = 1; off <= 2; off <<= 1) {
        s0 += __shfl_xor_sync(0xffffffffu, s0, off);
        s1 += __shfl_xor_sync(0xffffffffu, s1, off);
    }
    float* part = (float*)(smem + SM_PT);   // [32 rows][4 quarters]
    if ((lane & 3) == 0) {
        part[(rt * 16 + qrow)     * 4 + nh] = s0;
        part[(rt * 16 + qrow + 8) * 4 + nh] = s1;
    }
    __syncthreads();
    if (tid < 32) {
        float s = part[tid * 4] + part[tid * 4 + 1] + part[tid * 4 + 2] + part[tid * 4 + 3];
        out[t * 32 + tid] = s;
    }
}

extern "C" void kernel_launch(void* const* d_in, const int* in_sizes, int n_in,
                              void* d_out, int out_size)
{
    const int*   samples = (const int*)d_in[0];
    const float* eps     = (const float*)d_in[1];
    if (n_in >= 2 && in_sizes[0] == 2 * NM * NL && in_sizes[1] == NB * NL) {
        samples = (const int*)d_in[1];
        eps     = (const float*)d_in[0];
    }
    cudaFuncSetAttribute(qgps_fused_kernel,
                         cudaFuncAttributeMaxDynamicSharedMemorySize, SMEM);
    qgps_fused_kernel<<<NB / 32, 256, SMEM>>>(samples, eps, (float*)d_out);
}